// round 6
// baseline (speedup 1.0000x reference)
#include <cuda_runtime.h>
#include <cuda_bf16.h>

// CenterLossLayer: B=16384, C=1024, D=512, alpha=0.5
//   result[b]   = sum_d (features[b,d] - centers[labels[b],d])^2
//   delta[c,d]  = sum_{b: labels[b]==c} (centers[c,d] - features[b,d])
//   new_centers = centers - alpha * delta / (count_c + 1)
// d_out: [0..B) result f32 ; [B .. B+C*D) new_centers f32

#define BATCH       16384
#define NUM_CLASSES 1024
#define FEAT_DIM    512
#define ALPHA       0.5f

#define THREADS  128               // main kernel block size (one class per block)
#define NREP     4                 // 4 replica warps per class
#define CAPC     64                // bucket capacity per class (E[count]=16, max ~35)
#define NF4      (FEAT_DIM / 4)    // 128 float4 per row

#define F4_ZERO make_float4(0.f, 0.f, 0.f, 0.f)

__device__ int g_count[NUM_CLASSES];
__device__ int g_bucket[NUM_CLASSES][CAPC];

__device__ __forceinline__ float4 f4_sub(float4 a, float4 b) {
    return make_float4(a.x - b.x, a.y - b.y, a.z - b.z, a.w - b.w);
}
__device__ __forceinline__ void f4_acc(float4& a, float4 b) {
    a.x += b.x; a.y += b.y; a.z += b.z; a.w += b.w;
}
__device__ __forceinline__ float f4_dot(float4 a) {
    return a.x * a.x + a.y * a.y + a.z * a.z + a.w * a.w;
}

// ---------------------------------------------------------------------------
// Kernel 0: zero per-class counters
// ---------------------------------------------------------------------------
__global__ void zero_counts_kernel() {
    int tid = blockIdx.x * blockDim.x + threadIdx.x;
    if (tid < NUM_CLASSES) g_count[tid] = 0;
}

// ---------------------------------------------------------------------------
// Kernel 1: bin sample indices by class (labels read exactly once)
// ---------------------------------------------------------------------------
__global__ __launch_bounds__(256)
void bin_labels_kernel(const int* __restrict__ labels) {
    int tid = blockIdx.x * blockDim.x + threadIdx.x;   // 0 .. BATCH/4
    if (tid >= BATCH / 4) return;
    int4 L = reinterpret_cast<const int4*>(labels)[tid];
    int b0 = tid * 4;
    int ls[4] = {L.x, L.y, L.z, L.w};
    #pragma unroll
    for (int j = 0; j < 4; j++) {
        int c = ls[j];
        int pos = atomicAdd(&g_count[c], 1);
        if (pos < CAPC) g_bucket[c][pos] = b0 + j;
    }
}

// ---------------------------------------------------------------------------
// Kernel 2: one block per class. 4 replica warps, register accumulation,
// double-buffered feature loads. Finalize in-block.
// ---------------------------------------------------------------------------
__global__ __launch_bounds__(THREADS, 6)
void center_loss_main_kernel(const float* __restrict__ features,
                             const float* __restrict__ centers,
                             float*       __restrict__ out_result,
                             float*       __restrict__ out_centers) {
    __shared__ __align__(16) float s_center[FEAT_DIM];          // 2 KB
    __shared__ __align__(16) float s_delta[NREP * FEAT_DIM];    // 8 KB
    __shared__ int s_list[CAPC];
    __shared__ int s_cnt;

    const int t = threadIdx.x;
    const int c = blockIdx.x;

    // load center row: NF4 = 128 float4s == THREADS
    reinterpret_cast<float4*>(s_center)[t] =
        reinterpret_cast<const float4*>(centers + (size_t)c * FEAT_DIM)[t];

    // load bucket (<= CAPC entries)
    int cnt_raw = g_count[c];
    if (t == 0) s_cnt = min(cnt_raw, CAPC);
    if (t < CAPC) s_list[t] = g_bucket[c][t];
    __syncthreads();

    const int warp = t >> 5;          // replica id 0..3
    const int lane = t & 31;
    const int cnt  = s_cnt;

    // center row in registers (this lane's 16 floats)
    const float4* cen4 = reinterpret_cast<const float4*>(s_center);
    float4 c0v = cen4[lane +  0];
    float4 c1v = cen4[lane + 32];
    float4 c2v = cen4[lane + 64];
    float4 c3v = cen4[lane + 96];

    float4 a0 = F4_ZERO, a1 = F4_ZERO, a2 = F4_ZERO, a3 = F4_ZERO;

    int   i     = warp;
    int   b_cur = (i < cnt) ? s_list[i] : -1;
    float4 f0, f1, f2, f3;
    if (b_cur >= 0) {
        const float4* fr = reinterpret_cast<const float4*>(features + (size_t)b_cur * FEAT_DIM);
        f0 = fr[lane]; f1 = fr[lane + 32]; f2 = fr[lane + 64]; f3 = fr[lane + 96];
    }

    while (b_cur >= 0) {
        // prefetch next sample (overlaps current compute)
        int in = i + NREP;
        int b_next = (in < cnt) ? s_list[in] : -1;
        float4 n0, n1, n2, n3;
        if (b_next >= 0) {
            const float4* fr = reinterpret_cast<const float4*>(features + (size_t)b_next * FEAT_DIM);
            n0 = fr[lane]; n1 = fr[lane + 32]; n2 = fr[lane + 64]; n3 = fr[lane + 96];
        }

        float4 d0 = f4_sub(c0v, f0);
        float4 d1 = f4_sub(c1v, f1);
        float4 d2 = f4_sub(c2v, f2);
        float4 d3 = f4_sub(c3v, f3);
        f4_acc(a0, d0); f4_acc(a1, d1); f4_acc(a2, d2); f4_acc(a3, d3);
        float sq = f4_dot(d0) + f4_dot(d1) + f4_dot(d2) + f4_dot(d3);

        #pragma unroll
        for (int off = 16; off > 0; off >>= 1)
            sq += __shfl_down_sync(0xFFFFFFFFu, sq, off);
        if (lane == 0) out_result[b_cur] = sq;

        f0 = n0; f1 = n1; f2 = n2; f3 = n3;
        b_cur = b_next; i = in;
    }

    // write replica accumulator (full coverage — no zero-init needed)
    float4* dd = reinterpret_cast<float4*>(s_delta + (size_t)warp * FEAT_DIM);
    dd[lane] = a0; dd[lane + 32] = a1; dd[lane + 64] = a2; dd[lane + 96] = a3;
    __syncthreads();

    // finalize: reduce 4 replicas, new_centers = centers - alpha*delta/(count+1)
    {
        float s = ALPHA / (float)(cnt_raw + 1);
        const float4* base = reinterpret_cast<const float4*>(s_delta);
        float4 acc = base[0 * NF4 + t];
        f4_acc(acc, base[1 * NF4 + t]);
        f4_acc(acc, base[2 * NF4 + t]);
        f4_acc(acc, base[3 * NF4 + t]);

        float4 ce = reinterpret_cast<const float4*>(s_center)[t];
        float4 o;
        o.x = ce.x - s * acc.x;
        o.y = ce.y - s * acc.y;
        o.z = ce.z - s * acc.z;
        o.w = ce.w - s * acc.w;
        reinterpret_cast<float4*>(out_centers + (size_t)c * FEAT_DIM)[t] = o;
    }
}

// ---------------------------------------------------------------------------
extern "C" void kernel_launch(void* const* d_in, const int* in_sizes, int n_in,
                              void* d_out, int out_size) {
    const float* features = (const float*)d_in[0];
    const float* centers  = (const float*)d_in[1];
    const int*   labels   = (const int*)d_in[2];

    float* out_result      = (float*)d_out;          // [BATCH]
    float* out_new_centers = (float*)d_out + BATCH;  // [NUM_CLASSES * FEAT_DIM]

    zero_counts_kernel<<<NUM_CLASSES / 256, 256>>>();
    bin_labels_kernel<<<(BATCH / 4 + 255) / 256, 256>>>(labels);
    center_loss_main_kernel<<<NUM_CLASSES, THREADS>>>(
        features, centers, out_result, out_new_centers);
}

// round 7
// speedup vs baseline: 1.1530x; 1.1530x over previous
#include <cuda_runtime.h>
#include <cuda_bf16.h>

// CenterLossLayer: B=16384, C=1024, D=512, alpha=0.5
//   result[b]   = sum_d (features[b,d] - centers[labels[b],d])^2
//   delta[c,d]  = sum_{b: labels[b]==c} (centers[c,d] - features[b,d])
//   new_centers = centers - alpha * delta / (count_c + 1)
// d_out: [0..B) result f32 ; [B .. B+C*D) new_centers f32
//
// Single-launch design (graph-node overhead measured at ~3-4us/node):
// each block owns G=4 classes, scans labels once (L2-resident), processes
// matching feature rows with register accumulators (no atomics in hot loop).

#define BATCH       16384
#define NUM_CLASSES 1024
#define FEAT_DIM    512
#define ALPHA       0.5f

#define G        4                 // classes per block
#define THREADS  256
#define NWARPS   (THREADS / 32)    // 8
#define NREP     (NWARPS / G)      // 2 replica warps per class
#define CAPG     64                // per-class list capacity (E=16, max ~40)
#define NF4      (FEAT_DIM / 4)    // 128 float4 per row

#define F4_ZERO make_float4(0.f, 0.f, 0.f, 0.f)

__device__ __forceinline__ float4 f4_sub(float4 a, float4 b) {
    return make_float4(a.x - b.x, a.y - b.y, a.z - b.z, a.w - b.w);
}
__device__ __forceinline__ void f4_acc(float4& a, float4 b) {
    a.x += b.x; a.y += b.y; a.z += b.z; a.w += b.w;
}
__device__ __forceinline__ float f4_dot(float4 a) {
    return a.x * a.x + a.y * a.y + a.z * a.z + a.w * a.w;
}

__global__ __launch_bounds__(THREADS, 3)
void center_loss_fused_kernel(const float* __restrict__ features,
                              const float* __restrict__ centers,
                              const int*   __restrict__ labels,
                              float*       __restrict__ out_result,
                              float*       __restrict__ out_centers) {
    __shared__ __align__(16) float s_centers[G * FEAT_DIM];          // 8 KB
    __shared__ __align__(16) float s_delta[G * NREP * FEAT_DIM];     // 16 KB
    __shared__ int s_list[G][CAPG];                                  // 1 KB
    __shared__ int s_gcnt[G];

    const int t  = threadIdx.x;
    const int c0 = blockIdx.x * G;

    if (t < G) s_gcnt[t] = 0;
    // load G center rows: G*NF4 = 512 float4s, 256 threads -> 2 each
    {
        const float4* src = reinterpret_cast<const float4*>(centers + (size_t)c0 * FEAT_DIM);
        float4* dst = reinterpret_cast<float4*>(s_centers);
        dst[t]           = src[t];
        dst[t + THREADS] = src[t + THREADS];
    }
    __syncthreads();

    // ---- scan labels once per block (64 KB, L2-resident chip-wide) ----
    const int4* lab4 = reinterpret_cast<const int4*>(labels);
    #pragma unroll
    for (int i = 0; i < BATCH / 4 / THREADS; i++) {        // 16 iterations
        int idx4 = i * THREADS + t;                        // coalesced
        int4 L = lab4[idx4];
        int b0 = idx4 * 4;
        int ls[4] = {L.x, L.y, L.z, L.w};
        #pragma unroll
        for (int j = 0; j < 4; j++) {
            int g = ls[j] - c0;
            if ((unsigned)g < (unsigned)G) {
                int pos = atomicAdd(&s_gcnt[g], 1);
                if (pos < CAPG) s_list[g][pos] = b0 + j;
            }
        }
    }
    __syncthreads();

    // ---- warp-per-class (2 replicas), register accumulation, prefetch ----
    const int warp = t >> 5;
    const int lane = t & 31;
    const int g    = warp & (G - 1);           // class within group
    const int r    = warp >> 2;                // replica id 0..NREP-1
    const int cnt  = min(s_gcnt[g], CAPG);

    // center row cached in registers (this lane's 16 floats)
    const float4* cen4 = reinterpret_cast<const float4*>(s_centers + g * FEAT_DIM);
    float4 c0v = cen4[lane +  0];
    float4 c1v = cen4[lane + 32];
    float4 c2v = cen4[lane + 64];
    float4 c3v = cen4[lane + 96];

    float4 a0 = F4_ZERO, a1 = F4_ZERO, a2 = F4_ZERO, a3 = F4_ZERO;

    int   i     = r;
    int   b_cur = (i < cnt) ? s_list[g][i] : -1;
    float4 f0, f1, f2, f3;
    if (b_cur >= 0) {
        const float4* fr = reinterpret_cast<const float4*>(features + (size_t)b_cur * FEAT_DIM);
        f0 = fr[lane]; f1 = fr[lane + 32]; f2 = fr[lane + 64]; f3 = fr[lane + 96];
    }

    while (b_cur >= 0) {
        // prefetch next sample (overlaps current compute)
        int in = i + NREP;
        int b_next = (in < cnt) ? s_list[g][in] : -1;
        float4 n0, n1, n2, n3;
        if (b_next >= 0) {
            const float4* fr = reinterpret_cast<const float4*>(features + (size_t)b_next * FEAT_DIM);
            n0 = fr[lane]; n1 = fr[lane + 32]; n2 = fr[lane + 64]; n3 = fr[lane + 96];
        }

        float4 d0 = f4_sub(c0v, f0);
        float4 d1 = f4_sub(c1v, f1);
        float4 d2 = f4_sub(c2v, f2);
        float4 d3 = f4_sub(c3v, f3);
        f4_acc(a0, d0); f4_acc(a1, d1); f4_acc(a2, d2); f4_acc(a3, d3);
        float sq = f4_dot(d0) + f4_dot(d1) + f4_dot(d2) + f4_dot(d3);

        #pragma unroll
        for (int off = 16; off > 0; off >>= 1)
            sq += __shfl_down_sync(0xFFFFFFFFu, sq, off);
        if (lane == 0) out_result[b_cur] = sq;

        f0 = n0; f1 = n1; f2 = n2; f3 = n3;
        b_cur = b_next; i = in;
    }

    // write replica accumulator (plain STS, full coverage — no init needed)
    float4* dd = reinterpret_cast<float4*>(s_delta + (size_t)(g * NREP + r) * FEAT_DIM);
    dd[lane] = a0; dd[lane + 32] = a1; dd[lane + 64] = a2; dd[lane + 96] = a3;
    __syncthreads();

    // ---- finalize: reduce 2 replicas; new_centers = centers - a*delta/(cnt+1)
    // G*NF4 = 512 float4 outputs, 256 threads -> 2 each
    #pragma unroll
    for (int k = 0; k < 2; k++) {
        int idx = k * THREADS + t;         // 0..511
        int gg  = idx / NF4;               // class within group
        int q   = idx % NF4;
        float s = ALPHA / (float)(s_gcnt[gg] + 1);

        const float4* base = reinterpret_cast<const float4*>(s_delta);
        float4 acc = base[(gg * NREP + 0) * NF4 + q];
        f4_acc(acc, base[(gg * NREP + 1) * NF4 + q]);

        float4 ce = reinterpret_cast<const float4*>(s_centers)[idx];
        float4 o;
        o.x = ce.x - s * acc.x;
        o.y = ce.y - s * acc.y;
        o.z = ce.z - s * acc.z;
        o.w = ce.w - s * acc.w;
        reinterpret_cast<float4*>(out_centers + (size_t)c0 * FEAT_DIM)[idx] = o;
    }
}

// ---------------------------------------------------------------------------
extern "C" void kernel_launch(void* const* d_in, const int* in_sizes, int n_in,
                              void* d_out, int out_size) {
    const float* features = (const float*)d_in[0];
    const float* centers  = (const float*)d_in[1];
    const int*   labels   = (const int*)d_in[2];

    float* out_result      = (float*)d_out;          // [BATCH]
    float* out_new_centers = (float*)d_out + BATCH;  // [NUM_CLASSES * FEAT_DIM]

    center_loss_fused_kernel<<<NUM_CLASSES / G, THREADS>>>(
        features, centers, labels, out_result, out_new_centers);
}

// round 8
// speedup vs baseline: 1.1555x; 1.0022x over previous
#include <cuda_runtime.h>
#include <cuda_bf16.h>

// CenterLossLayer: B=16384, C=1024, D=512, alpha=0.5
//   result[b]   = sum_d (features[b,d] - centers[labels[b],d])^2
//   delta[c,d]  = sum_{b: labels[b]==c} (centers[c,d] - features[b,d])
//   new_centers = centers - alpha * delta / (count_c + 1)
// d_out: [0..B) result f32 ; [B .. B+C*D) new_centers f32
//
// Single launch. Grid=296 (=2x148 SMs, exact 2 blocks/SM). Block owns a
// contiguous range of 3-4 classes; warps share the block's sample list via
// contiguous chunks (dynamic balance); register accumulators flushed to smem
// via atomicAdd only on (rare) class transitions.

#define BATCH       16384
#define NUM_CLASSES 1024
#define FEAT_DIM    512
#define ALPHA       0.5f

#define NBLK     296
#define THREADS  256
#define NWARPS   8
#define GMAX     4                 // max classes per block (ceil(1024/296)=4)
#define CAPG     96                // per-class capacity (E=16, max ~40)
#define NF4      (FEAT_DIM / 4)

#define F4_ZERO make_float4(0.f, 0.f, 0.f, 0.f)

__device__ __forceinline__ float4 f4_sub(float4 a, float4 b) {
    return make_float4(a.x - b.x, a.y - b.y, a.z - b.z, a.w - b.w);
}
__device__ __forceinline__ void f4_acc(float4& a, float4 b) {
    a.x += b.x; a.y += b.y; a.z += b.z; a.w += b.w;
}
__device__ __forceinline__ float f4_dot(float4 a) {
    return a.x * a.x + a.y * a.y + a.z * a.z + a.w * a.w;
}

__global__ __launch_bounds__(THREADS, 2)
void center_loss_kernel(const float* __restrict__ features,
                        const float* __restrict__ centers,
                        const int*   __restrict__ labels,
                        float*       __restrict__ out_result,
                        float*       __restrict__ out_centers) {
    __shared__ __align__(16) float s_centers[GMAX * FEAT_DIM];   // 8 KB
    __shared__ __align__(16) float s_delta[GMAX * FEAT_DIM];     // 8 KB
    __shared__ int s_list[GMAX][CAPG];                           // 1.5 KB
    __shared__ int s_gcnt[GMAX];

    const int t   = threadIdx.x;
    const int bid = blockIdx.x;
    const int lo  = (bid * NUM_CLASSES) / NBLK;
    const int hi  = ((bid + 1) * NUM_CLASSES) / NBLK;
    const int nc  = hi - lo;                                     // 3 or 4

    if (t < GMAX) s_gcnt[t] = 0;
    {
        const float4* src = reinterpret_cast<const float4*>(centers + (size_t)lo * FEAT_DIM);
        float4* dst = reinterpret_cast<float4*>(s_centers);
        float4* dz  = reinterpret_cast<float4*>(s_delta);
        #pragma unroll
        for (int k = 0; k < 2; k++) {
            int idx = k * THREADS + t;                           // 0..511
            if (idx < nc * NF4) dst[idx] = src[idx];
            dz[idx] = F4_ZERO;
        }
    }
    __syncthreads();

    // ---- scan labels once per block (64 KB, L2-resident chip-wide) ----
    const int4* lab4 = reinterpret_cast<const int4*>(labels);
    #pragma unroll
    for (int i = 0; i < BATCH / 4 / THREADS; i++) {              // 16 iterations
        int idx4 = i * THREADS + t;
        int4 L = lab4[idx4];
        int b0 = idx4 * 4;
        int ls[4] = {L.x, L.y, L.z, L.w};
        #pragma unroll
        for (int j = 0; j < 4; j++) {
            int g = ls[j] - lo;
            if ((unsigned)g < (unsigned)nc) {
                int pos = atomicAdd(&s_gcnt[g], 1);
                if (pos < CAPG) s_list[g][pos] = b0 + j;
            }
        }
    }
    __syncthreads();

    // ---- flat ordering over the block's samples; warp takes a chunk ----
    const int cnt0 = min(s_gcnt[0], CAPG);
    const int cnt1 = (nc > 1) ? min(s_gcnt[1], CAPG) : 0;
    const int cnt2 = (nc > 2) ? min(s_gcnt[2], CAPG) : 0;
    const int cnt3 = (nc > 3) ? min(s_gcnt[3], CAPG) : 0;
    const int o1 = cnt0, o2 = o1 + cnt1, o3 = o2 + cnt2;
    const int total = o3 + cnt3;

    const int warp = t >> 5;
    const int lane = t & 31;
    const int js = (total * warp) / NWARPS;
    const int je = (total * (warp + 1)) / NWARPS;

    float4 c0v, c1v, c2v, c3v;
    float4 a0 = F4_ZERO, a1 = F4_ZERO, a2 = F4_ZERO, a3 = F4_ZERO;
    float4 f0, f1, f2, f3;

    int j = js, g_cur = -1, b_cur = -1;
    if (j < je) {
        int base;
        if      (j < o1) { g_cur = 0; base = 0;  }
        else if (j < o2) { g_cur = 1; base = o1; }
        else if (j < o3) { g_cur = 2; base = o2; }
        else             { g_cur = 3; base = o3; }
        b_cur = s_list[g_cur][j - base];
        const float4* cen = reinterpret_cast<const float4*>(s_centers + g_cur * FEAT_DIM);
        c0v = cen[lane]; c1v = cen[lane + 32]; c2v = cen[lane + 64]; c3v = cen[lane + 96];
        const float4* fr = reinterpret_cast<const float4*>(features + (size_t)b_cur * FEAT_DIM);
        f0 = fr[lane]; f1 = fr[lane + 32]; f2 = fr[lane + 64]; f3 = fr[lane + 96];
    }

    while (j < je) {
        // prefetch next sample (overlaps current compute)
        int jn = j + 1, g_next = -1, b_next = -1;
        float4 n0, n1, n2, n3;
        if (jn < je) {
            int base;
            if      (jn < o1) { g_next = 0; base = 0;  }
            else if (jn < o2) { g_next = 1; base = o1; }
            else if (jn < o3) { g_next = 2; base = o2; }
            else              { g_next = 3; base = o3; }
            b_next = s_list[g_next][jn - base];
            const float4* fr = reinterpret_cast<const float4*>(features + (size_t)b_next * FEAT_DIM);
            n0 = fr[lane]; n1 = fr[lane + 32]; n2 = fr[lane + 64]; n3 = fr[lane + 96];
        }

        // process current sample
        float4 d0 = f4_sub(c0v, f0);
        float4 d1 = f4_sub(c1v, f1);
        float4 d2 = f4_sub(c2v, f2);
        float4 d3 = f4_sub(c3v, f3);
        f4_acc(a0, d0); f4_acc(a1, d1); f4_acc(a2, d2); f4_acc(a3, d3);
        float sq = f4_dot(d0) + f4_dot(d1) + f4_dot(d2) + f4_dot(d3);

        #pragma unroll
        for (int off = 16; off > 0; off >>= 1)
            sq += __shfl_down_sync(0xFFFFFFFFu, sq, off);
        if (lane == 0) out_result[b_cur] = sq;

        // flush accumulator on class transition or end of chunk (warp-uniform)
        if (g_next != g_cur) {
            float* dst = s_delta + g_cur * FEAT_DIM;
            atomicAdd(dst + 4 * lane + 0,         a0.x);
            atomicAdd(dst + 4 * lane + 1,         a0.y);
            atomicAdd(dst + 4 * lane + 2,         a0.z);
            atomicAdd(dst + 4 * lane + 3,         a0.w);
            atomicAdd(dst + 4 * (lane + 32) + 0,  a1.x);
            atomicAdd(dst + 4 * (lane + 32) + 1,  a1.y);
            atomicAdd(dst + 4 * (lane + 32) + 2,  a1.z);
            atomicAdd(dst + 4 * (lane + 32) + 3,  a1.w);
            atomicAdd(dst + 4 * (lane + 64) + 0,  a2.x);
            atomicAdd(dst + 4 * (lane + 64) + 1,  a2.y);
            atomicAdd(dst + 4 * (lane + 64) + 2,  a2.z);
            atomicAdd(dst + 4 * (lane + 64) + 3,  a2.w);
            atomicAdd(dst + 4 * (lane + 96) + 0,  a3.x);
            atomicAdd(dst + 4 * (lane + 96) + 1,  a3.y);
            atomicAdd(dst + 4 * (lane + 96) + 2,  a3.z);
            atomicAdd(dst + 4 * (lane + 96) + 3,  a3.w);
            a0 = F4_ZERO; a1 = F4_ZERO; a2 = F4_ZERO; a3 = F4_ZERO;
            if (jn < je) {
                const float4* cen = reinterpret_cast<const float4*>(s_centers + g_next * FEAT_DIM);
                c0v = cen[lane]; c1v = cen[lane + 32]; c2v = cen[lane + 64]; c3v = cen[lane + 96];
            }
        }

        f0 = n0; f1 = n1; f2 = n2; f3 = n3;
        b_cur = b_next; g_cur = g_next; j = jn;
    }
    __syncthreads();

    // ---- finalize: new_centers = centers - alpha * delta / (count + 1) ----
    #pragma unroll
    for (int k = 0; k < 2; k++) {
        int idx = k * THREADS + t;                 // 0..511
        int gg  = idx / NF4;
        if (gg < nc) {
            float s = ALPHA / (float)(s_gcnt[gg] + 1);
            float4 de = reinterpret_cast<const float4*>(s_delta)[idx];
            float4 ce = reinterpret_cast<const float4*>(s_centers)[idx];
            float4 o;
            o.x = ce.x - s * de.x;
            o.y = ce.y - s * de.y;
            o.z = ce.z - s * de.z;
            o.w = ce.w - s * de.w;
            reinterpret_cast<float4*>(out_centers + (size_t)lo * FEAT_DIM)[idx] = o;
        }
    }
}

// ---------------------------------------------------------------------------
extern "C" void kernel_launch(void* const* d_in, const int* in_sizes, int n_in,
                              void* d_out, int out_size) {
    const float* features = (const float*)d_in[0];
    const float* centers  = (const float*)d_in[1];
    const int*   labels   = (const int*)d_in[2];

    float* out_result      = (float*)d_out;          // [BATCH]
    float* out_new_centers = (float*)d_out + BATCH;  // [NUM_CLASSES * FEAT_DIM]

    center_loss_kernel<<<NBLK, THREADS>>>(
        features, centers, labels, out_result, out_new_centers);
}